// round 17
// baseline (speedup 1.0000x reference)
#include <cuda_runtime.h>
#include <cuda_fp16.h>

#define NN 100000
#define FD 32
#define EPT 4   // edges per scatter thread-group

// Scratch (static device globals — no allocation in kernel_launch).
// g_deg is zero-initialized at module load and RE-ZEROED by k_final each
// call, so k_count can accumulate from zero on every graph replay.
__device__ __half g_sc[NN * FD];    // messages (fp16), gather side
__device__ __half g_aggh[NN * FD];  // fp16 accumulator, seeded with self-loop
__device__ float  g_dinv[NN];
__device__ int    g_deg[NN];        // in-degree WITHOUT self-loop

__global__ void k_count(const int* __restrict__ dst, int E) {
    cudaTriggerProgrammaticLaunchCompletion();
    int t = blockIdx.x * blockDim.x + threadIdx.x;
    int e = t * 4;
    cudaGridDependencySynchronize();   // first kernel: no-op, kept for uniformity
    if (e + 3 < E) {
        int4 d = *reinterpret_cast<const int4*>(dst + e);
        atomicAdd(&g_deg[d.x], 1);
        atomicAdd(&g_deg[d.y], 1);
        atomicAdd(&g_deg[d.z], 1);
        atomicAdd(&g_deg[d.w], 1);
    } else {
        for (int i = e; i < E; i++) atomicAdd(&g_deg[dst[i]], 1);
    }
}

// Node-per-thread: 8x LDG.128 of x row (MLP=8, DRAM latency covered),
// dinv = rsqrt(deg+1) (self-loop folded), packed fp16 row stores.
__global__ void k_scale0(const float* __restrict__ x) {
    cudaTriggerProgrammaticLaunchCompletion();
    int node = blockIdx.x * blockDim.x + threadIdx.x;
    if (node >= NN) return;
    const float4* xr = reinterpret_cast<const float4*>(x + (size_t)node * FD);
    float4 v[8];
    #pragma unroll
    for (int j = 0; j < 8; j++) v[j] = __ldg(xr + j);   // input-only, early
    cudaGridDependencySynchronize();                     // wait k_count
    float dv = rsqrtf((float)(g_deg[node] + 1));
    g_dinv[node] = dv;
    uint4 o[4];
    #pragma unroll
    for (int j = 0; j < 4; j++) {
        __half2 a0 = __floats2half2_rn(v[2*j].x * dv,   v[2*j].y * dv);
        __half2 a1 = __floats2half2_rn(v[2*j].z * dv,   v[2*j].w * dv);
        __half2 a2 = __floats2half2_rn(v[2*j+1].x * dv, v[2*j+1].y * dv);
        __half2 a3 = __floats2half2_rn(v[2*j+1].z * dv, v[2*j+1].w * dv);
        o[j].x = *reinterpret_cast<unsigned int*>(&a0);
        o[j].y = *reinterpret_cast<unsigned int*>(&a1);
        o[j].z = *reinterpret_cast<unsigned int*>(&a2);
        o[j].w = *reinterpret_cast<unsigned int*>(&a3);
    }
    uint4* psc = reinterpret_cast<uint4*>(g_sc   + (size_t)node * FD);
    uint4* pag = reinterpret_cast<uint4*>(g_aggh + (size_t)node * FD);
    #pragma unroll
    for (int j = 0; j < 4; j++) { psc[j] = o[j]; pag[j] = o[j]; }
}

// Scatter: 4 lanes per edge (lane covers 8 fp16 = 16B), 4 edges per thread.
// Raw-bit uint4 gather + fp16x2 v4 RED (ISA max width). At the RED wall.
__global__ __launch_bounds__(256) void k_scatter(const int* __restrict__ src,
                                                 const int* __restrict__ dst,
                                                 int E) {
    cudaTriggerProgrammaticLaunchCompletion();
    long long t = (long long)blockIdx.x * 256 + threadIdx.x;
    int e0 = (int)(t >> 2) * EPT;
    if (e0 >= E) return;
    int q = ((int)t & 3) << 3;   // feature offset 0,8,16,24 (halves)

    if (e0 + EPT <= E) {
        int4 s4 = *reinterpret_cast<const int4*>(src + e0);  // input, early
        int4 d4 = *reinterpret_cast<const int4*>(dst + e0);
        cudaGridDependencySynchronize();                      // wait producer

        uint4 v0 = *reinterpret_cast<const uint4*>(g_sc + (size_t)s4.x * FD + q);
        uint4 v1 = *reinterpret_cast<const uint4*>(g_sc + (size_t)s4.y * FD + q);
        uint4 v2 = *reinterpret_cast<const uint4*>(g_sc + (size_t)s4.z * FD + q);
        uint4 v3 = *reinterpret_cast<const uint4*>(g_sc + (size_t)s4.w * FD + q);

        __half* a0 = g_aggh + (size_t)d4.x * FD + q;
        __half* a1 = g_aggh + (size_t)d4.y * FD + q;
        __half* a2 = g_aggh + (size_t)d4.z * FD + q;
        __half* a3 = g_aggh + (size_t)d4.w * FD + q;
        asm volatile("red.global.add.noftz.v4.f16x2 [%0], {%1, %2, %3, %4};"
                     :: "l"(a0), "r"(v0.x), "r"(v0.y), "r"(v0.z), "r"(v0.w) : "memory");
        asm volatile("red.global.add.noftz.v4.f16x2 [%0], {%1, %2, %3, %4};"
                     :: "l"(a1), "r"(v1.x), "r"(v1.y), "r"(v1.z), "r"(v1.w) : "memory");
        asm volatile("red.global.add.noftz.v4.f16x2 [%0], {%1, %2, %3, %4};"
                     :: "l"(a2), "r"(v2.x), "r"(v2.y), "r"(v2.z), "r"(v2.w) : "memory");
        asm volatile("red.global.add.noftz.v4.f16x2 [%0], {%1, %2, %3, %4};"
                     :: "l"(a3), "r"(v3.x), "r"(v3.y), "r"(v3.z), "r"(v3.w) : "memory");
    } else {
        cudaGridDependencySynchronize();
        for (int e = e0; e < E; e++) {
            int s = src[e];
            int d = dst[e];
            uint4 v = *reinterpret_cast<const uint4*>(g_sc + (size_t)s * FD + q);
            __half* a = g_aggh + (size_t)d * FD + q;
            asm volatile("red.global.add.noftz.v4.f16x2 [%0], {%1, %2, %3, %4};"
                         :: "l"(a), "r"(v.x), "r"(v.y), "r"(v.z), "r"(v.w) : "memory");
        }
    }
}

// Mid: ph = dinv*agg0; h1 = relu(ph @ W0 + b0); msg1 = fp16(dinv*h1).
// ILP version: stage all 8 node-rows, ONE syncwarp, 8 interleaved GEMVs.
__global__ __launch_bounds__(256) void k_mid(const float* __restrict__ W0,
                                             const float* __restrict__ b0) {
    cudaTriggerProgrammaticLaunchCompletion();
    __shared__ float Ws[FD * FD];
    __shared__ float s_row[8][8][FD];   // [warp][node][feature], 8KB
    int tid = threadIdx.x;
    int lane = tid & 31;
    int wb = tid >> 5;
    #pragma unroll
    for (int i = tid; i < FD * FD; i += 256) Ws[i] = W0[i];  // input, early
    float bl = b0[lane];
    __syncthreads();

    float Wc[FD];
    #pragma unroll
    for (int k = 0; k < FD; k++) Wc[k] = Ws[k * FD + lane];

    int base = (blockIdx.x * 8 + wb) * 8;    // 8 nodes per warp
    if (base >= NN) return;

    cudaGridDependencySynchronize();         // wait scatter1

    __half vh[8];
    float dvv[8];
    #pragma unroll
    for (int u = 0; u < 8; u++) {            // batched loads, MLP=8
        vh[u]  = g_aggh[(size_t)(base + u) * FD + lane];
        dvv[u] = __ldg(&g_dinv[base + u]);
    }
    #pragma unroll
    for (int u = 0; u < 8; u++)
        s_row[wb][u][lane] = dvv[u] * __half2float(vh[u]);
    __syncwarp();

    float acc[8] = {0, 0, 0, 0, 0, 0, 0, 0};
    #pragma unroll
    for (int j = 0; j < FD / 4; j++) {       // j-outer: Wc reuse, 8-way ILP
        #pragma unroll
        for (int u = 0; u < 8; u++) {
            float4 t4 = *reinterpret_cast<const float4*>(&s_row[wb][u][4 * j]);
            acc[u] = fmaf(t4.x, Wc[4 * j + 0], acc[u]);
            acc[u] = fmaf(t4.y, Wc[4 * j + 1], acc[u]);
            acc[u] = fmaf(t4.z, Wc[4 * j + 2], acc[u]);
            acc[u] = fmaf(t4.w, Wc[4 * j + 3], acc[u]);
        }
    }
    #pragma unroll
    for (int u = 0; u < 8; u++) {
        int node = base + u;
        __half s1 = __float2half(dvv[u] * fmaxf(acc[u] + bl, 0.0f));
        g_sc[(size_t)node * FD + lane]   = s1;
        g_aggh[(size_t)node * FD + lane] = s1;
    }
}

// Final: ph = dinv*agg1; h2 = relu(ph @ W1 + b1); out = h2 @ Wf + bf.
// Also re-zeroes g_deg (this call's last consumer was k_scale0) so the
// next graph replay starts from a clean degree array.
__global__ __launch_bounds__(256) void k_final(const float* __restrict__ W1,
                                               const float* __restrict__ b1,
                                               const float* __restrict__ Wf,
                                               const float* __restrict__ bf,
                                               float* __restrict__ out) {
    cudaTriggerProgrammaticLaunchCompletion();
    __shared__ float Ws1[FD * FD];
    __shared__ float Wsf[FD * FD];
    __shared__ float s_row[8][8][FD];
    int tid = threadIdx.x;
    int lane = tid & 31;
    int wb = tid >> 5;
    #pragma unroll
    for (int i = tid; i < FD * FD; i += 256) { Ws1[i] = W1[i]; Wsf[i] = Wf[i]; }
    float b1l = b1[lane];
    float bfl = bf[lane];
    __syncthreads();

    cudaGridDependencySynchronize();         // wait scatter2

    // Re-zero this block's slice of g_deg (64 nodes per block).
    {
        int z = blockIdx.x * 64 + tid;
        if (tid < 64 && z < NN) g_deg[z] = 0;
    }

    int base = (blockIdx.x * 8 + wb) * 8;
    if (base >= NN) return;

    __half vh[8];
    float dvv[8];
    #pragma unroll
    for (int u = 0; u < 8; u++) {
        vh[u]  = g_aggh[(size_t)(base + u) * FD + lane];
        dvv[u] = __ldg(&g_dinv[base + u]);
    }
    #pragma unroll
    for (int u = 0; u < 8; u++)
        s_row[wb][u][lane] = dvv[u] * __half2float(vh[u]);
    __syncwarp();

    // Stage 1: h2 = relu(ph @ W1 + b1)
    {
        float Wc[FD];
        #pragma unroll
        for (int k = 0; k < FD; k++) Wc[k] = Ws1[k * FD + lane];
        float acc[8] = {0, 0, 0, 0, 0, 0, 0, 0};
        #pragma unroll
        for (int j = 0; j < FD / 4; j++) {
            #pragma unroll
            for (int u = 0; u < 8; u++) {
                float4 t4 = *reinterpret_cast<const float4*>(&s_row[wb][u][4 * j]);
                acc[u] = fmaf(t4.x, Wc[4 * j + 0], acc[u]);
                acc[u] = fmaf(t4.y, Wc[4 * j + 1], acc[u]);
                acc[u] = fmaf(t4.z, Wc[4 * j + 2], acc[u]);
                acc[u] = fmaf(t4.w, Wc[4 * j + 3], acc[u]);
            }
        }
        __syncwarp();                        // all reads of s_row done
        #pragma unroll
        for (int u = 0; u < 8; u++)
            s_row[wb][u][lane] = fmaxf(acc[u] + b1l, 0.0f);
        __syncwarp();
    }

    // Stage 2: out = h2 @ Wf + bf
    {
        float Wc[FD];
        #pragma unroll
        for (int k = 0; k < FD; k++) Wc[k] = Wsf[k * FD + lane];
        float acc[8];
        #pragma unroll
        for (int u = 0; u < 8; u++) acc[u] = bfl;
        #pragma unroll
        for (int j = 0; j < FD / 4; j++) {
            #pragma unroll
            for (int u = 0; u < 8; u++) {
                float4 t4 = *reinterpret_cast<const float4*>(&s_row[wb][u][4 * j]);
                acc[u] = fmaf(t4.x, Wc[4 * j + 0], acc[u]);
                acc[u] = fmaf(t4.y, Wc[4 * j + 1], acc[u]);
                acc[u] = fmaf(t4.z, Wc[4 * j + 2], acc[u]);
                acc[u] = fmaf(t4.w, Wc[4 * j + 3], acc[u]);
            }
        }
        #pragma unroll
        for (int u = 0; u < 8; u++)
            out[(size_t)(base + u) * FD + lane] = acc[u];
    }
}

extern "C" void kernel_launch(void* const* d_in, const int* in_sizes, int n_in,
                              void* d_out, int out_size) {
    const float* x   = (const float*)d_in[0];
    const int*   ei  = (const int*)d_in[1];   // JAX x64 disabled -> int32
    const float* W0  = (const float*)d_in[2];
    const float* b0  = (const float*)d_in[3];
    const float* W1  = (const float*)d_in[4];
    const float* b1  = (const float*)d_in[5];
    const float* Wf  = (const float*)d_in[6];
    const float* bf  = (const float*)d_in[7];
    float* out = (float*)d_out;

    int E = in_sizes[1] / 2;          // edge_index is [2, E]
    const int* src = ei;
    const int* dst = ei + E;

    int nb_n  = (NN + 255) / 256;                // 391 (node-per-thread scale0)
    int nb_c  = ((E + 3) / 4 + 255) / 256;
    int nb_x  = (NN / 8 + 7) / 8;                // 1563 blocks (8 warps each)
    long long sthreads = (long long)((E + EPT - 1) / EPT) * 4;
    int nb_s  = (int)((sthreads + 255) / 256);

    // PDL: device-side cudaGridDependencySynchronize() guards data deps.
    cudaLaunchConfig_t cfg = {};
    cudaLaunchAttribute at[1];
    at[0].id = cudaLaunchAttributeProgrammaticStreamSerialization;
    at[0].val.programmaticStreamSerializationAllowed = 1;
    cfg.attrs = at;
    cfg.numAttrs = 1;
    cfg.blockDim = dim3(256, 1, 1);
    cfg.stream = 0;

    cfg.gridDim = dim3(nb_c, 1, 1);
    cudaLaunchKernelEx(&cfg, k_count, dst, E);

    cfg.gridDim = dim3(nb_n, 1, 1);
    cudaLaunchKernelEx(&cfg, k_scale0, x);

    cfg.gridDim = dim3(nb_s, 1, 1);
    cudaLaunchKernelEx(&cfg, k_scatter, src, dst, E);

    cfg.gridDim = dim3(nb_x, 1, 1);
    cudaLaunchKernelEx(&cfg, k_mid, W0, b0);

    cfg.gridDim = dim3(nb_s, 1, 1);
    cudaLaunchKernelEx(&cfg, k_scatter, src, dst, E);

    cfg.gridDim = dim3(nb_x, 1, 1);
    cudaLaunchKernelEx(&cfg, k_final, W1, b1, Wf, bf, out);
}